// round 11
// baseline (speedup 1.0000x reference)
#include <cuda_runtime.h>

// RSI fused single pass, v11. out[c] = g/(g+l) over 13-wide window of
// positive/negative relative deltas (0 when no losses in window).
//
// v8 skeleton, store path deleted: warp output ranges are shifted by the
// row-uniform alignment phase s so each thread's 16 consecutive outputs are
// 16B-aligned -> 4 direct STG.128 from registers. No ov smem, no transpose.
// Shift absorbed by consuming 12+s neighbor p-values (templated S: all
// indices compile-time). Head outputs (o < s) done by block0/warp0/lane0.

#define NROWS  2048
#define NCOLS  8192
#define TPB    256
#define ITEMS  16
#define WTILE  512
#define TILE   4096
#define MAXW   64
#define SLOT   20                 // p floats per lane slot (16 data + 4 pad)
#define PREG   (SLOT * 33 + 4)    // 32 lanes + halo slot

template <int S>
__device__ __forceinline__ void win_store(
    const float* __restrict__ p,   // own p[0..15]
    const float* __restrict__ n,   // neighbor p[0..15] (n[15] unused)
    float* __restrict__ rout,
    int wbase, int out_cols, int lane, bool edgew)
{
    // v[j]: window source values, j = 0..30 (S+27 <= 30)
    float v[31];
    #pragma unroll
    for (int i = 0; i < 16; ++i) v[i] = p[i];
    #pragma unroll
    for (int i = 0; i < 15; ++i) v[16 + i] = n[i];

    const int tbase = wbase + S + 16 * lane;   // thread's first output col

    float Sw = 0.0f, L = 0.0f;
    float ql[ITEMS], ov4[4];
    #pragma unroll
    for (int jj = 0; jj < 28; ++jj) {
        const int j = S + jj;                  // compile-time
        if (jj < 16) ql[jj] = L;
        const float vj = v[j];
        L  += fmaxf(-vj, 0.0f);                // exact loss prefix
        Sw += vj;
        if (jj >= 13) Sw -= v[j - 13];         // sliding signed window
        if (jj >= 12) {
            const int k = jj - 12;             // output index 0..15
            const float l = L - ql[k];
            const float t = Sw + l;            // g = Sw + l
            ov4[k & 3] = (l != 0.0f) ? __fdividef(t, t + l) : 0.0f;
            if ((k & 3) == 3) {
                if (!edgew) {
                    *(float4*)(rout + tbase + (k - 3)) =     // 16B-aligned
                        make_float4(ov4[0], ov4[1], ov4[2], ov4[3]);
                } else {
                    #pragma unroll
                    for (int c = 0; c < 4; ++c) {
                        const int col = tbase + (k - 3) + c;
                        if (col < out_cols) rout[col] = ov4[c];
                    }
                }
            }
        }
    }

    // head outputs o = 0..S-1 (windows over p[o..o+12], all within own p)
    if (S > 0 && wbase == 0 && lane == 0) {
        #pragma unroll
        for (int o = 0; o < S; ++o) {
            float g = 0.0f, l = 0.0f;
            #pragma unroll
            for (int i = 0; i < 13; ++i) {
                const float vv = p[o + i];
                g += fmaxf(vv, 0.0f);
                l += fmaxf(-vv, 0.0f);
            }
            rout[o] = (l != 0.0f) ? __fdividef(g, g + l) : 0.0f;
        }
    }
}

__global__ __launch_bounds__(TPB) void rsi_v11(
    const float* __restrict__ in,
    float* __restrict__ out,
    int out_cols)
{
    __shared__ __align__(16) float s_p[8 * PREG];

    const int tid   = threadIdx.x;
    const int lane  = tid & 31;
    const int wrp   = tid >> 5;
    const int row   = blockIdx.y;
    const int wbase = blockIdx.x * TILE + wrp * WTILE;   // unshifted warp base
    const float* rin = in + (size_t)row * NCOLS;
    float* pw  = s_p + wrp * PREG;
    float* myp = pw + SLOT * lane;

    // ---- load own 16 inputs (g0+15 <= 8191 always) ----
    const int g0 = wbase + ITEMS * lane;
    const float4 xA = *(const float4*)(rin + g0);
    const float4 xB = *(const float4*)(rin + g0 + 4);
    const float4 xC = *(const float4*)(rin + g0 + 8);
    const float4 xD = *(const float4*)(rin + g0 + 12);

    float x16 = __shfl_down_sync(0xffffffffu, xA.x, 1);
    if (lane == 31)
        x16 = (g0 + 16 < NCOLS) ? rin[g0 + 16] : 0.0f;

    // halo x: lanes 0..15 load x[wbase+512+lane] (zero past row end)
    float xe = 0.0f;
    if (lane < 16) {
        const int ge = wbase + WTILE + lane;
        xe = (ge < NCOLS) ? rin[ge] : 0.0f;
    }
    const float xen = __shfl_down_sync(0xffffffffu, xe, 1);

    // ---- own 16 p-values ----
    const float xs[17] = {xA.x, xA.y, xA.z, xA.w, xB.x, xB.y, xB.z, xB.w,
                          xC.x, xC.y, xC.z, xC.w, xD.x, xD.y, xD.z, xD.w, x16};
    float p[ITEMS];
    #pragma unroll
    for (int c = 0; c < ITEMS; ++c) {
        const float prev = xs[c];
        p[c] = (prev != 0.0f) ? __fdividef(xs[c + 1] - prev, prev) : 0.0f;
    }

    // ---- publish p[0..15] (stride-20, conflict-free STS.128) ----
    *(float4*)(myp)      = make_float4(p[0],  p[1],  p[2],  p[3]);
    *(float4*)(myp + 4)  = make_float4(p[4],  p[5],  p[6],  p[7]);
    *(float4*)(myp + 8)  = make_float4(p[8],  p[9],  p[10], p[11]);
    *(float4*)(myp + 12) = make_float4(p[12], p[13], p[14], p[15]);
    // halo p -> slot 32 (lanes 0..14; slot[15] is never consumed)
    if (lane < 15) {
        const float pe = (xe != 0.0f) ? __fdividef(xen - xe, xe) : 0.0f;
        pw[SLOT * 32 + lane] = pe;
    }
    if (lane == 15) pw[SLOT * 32 + 15] = 0.0f;           // keep reads NaN-free
    __syncwarp();

    // ---- fetch 16 neighbor p-values (lane 31 -> halo slot) ----
    const float* nbp = pw + SLOT * (lane + 1);
    const float4 n0 = *(const float4*)(nbp);
    const float4 n1 = *(const float4*)(nbp + 4);
    const float4 n2 = *(const float4*)(nbp + 8);
    const float4 n3 = *(const float4*)(nbp + 12);
    const float n[16] = {n0.x, n0.y, n0.z, n0.w, n1.x, n1.y, n1.z, n1.w,
                         n2.x, n2.y, n2.z, n2.w, n3.x, n3.y, n3.z, n3.w};

    // ---- alignment phase (row-uniform) and dispatch ----
    const unsigned a0 = ((unsigned)row * (unsigned)out_cols) & 3u;
    const int s = (int)((4u - a0) & 3u);
    float* rout = out + (size_t)row * out_cols;
    // edge: shifted warp range may exceed valid outputs
    const bool edgew = (wbase + s + WTILE) > out_cols;

    switch (s) {
        case 0:  win_store<0>(p, n, rout, wbase, out_cols, lane, edgew); break;
        case 1:  win_store<1>(p, n, rout, wbase, out_cols, lane, edgew); break;
        case 2:  win_store<2>(p, n, rout, wbase, out_cols, lane, edgew); break;
        default: win_store<3>(p, n, rout, wbase, out_cols, lane, edgew); break;
    }
}

// ---- Generic fallback for unexpected window sizes ----
__global__ __launch_bounds__(TPB) void rsi_generic(
    const float* __restrict__ in,
    float* __restrict__ out,
    int out_cols, int w)
{
    __shared__ float s_in[TPB + MAXW + 1];
    __shared__ float s_g [TPB + MAXW];
    __shared__ float s_l [TPB + MAXW];

    const int row  = blockIdx.y;
    const int base = blockIdx.x * TPB;
    const float* rin = in + (size_t)row * NCOLS;

    const int need_in = TPB + w + 1;
    for (int i = threadIdx.x; i < need_in; i += TPB) {
        const int col = base + i;
        s_in[i] = (col < NCOLS) ? rin[col] : 0.0f;
    }
    __syncthreads();

    const int need_p = TPB + w;
    for (int i = threadIdx.x; i < need_p; i += TPB) {
        const float prev = s_in[i];
        const float cur  = s_in[i + 1];
        const float p = (prev != 0.0f) ? (cur - prev) / prev : 0.0f;
        s_g[i] = fmaxf(p, 0.0f);
        s_l[i] = fmaxf(-p, 0.0f);
    }
    __syncthreads();

    const int c = base + threadIdx.x;
    if (c < out_cols) {
        float g = 0.0f, l = 0.0f;
        for (int j = 0; j < w; ++j) {
            g += s_g[threadIdx.x + j];
            l += s_l[threadIdx.x + j];
        }
        out[(size_t)row * out_cols + c] = (l != 0.0f) ? g / (g + l) : 0.0f;
    }
}

extern "C" void kernel_launch(void* const* d_in, const int* in_sizes, int n_in,
                              void* d_out, int out_size)
{
    const float* in  = (const float*)d_in[0];
    float*       out = (float*)d_out;

    const int out_cols = out_size / NROWS;   // NCOLS - (window_size - 1)
    int w = NCOLS - out_cols;

    if (w == 13) {
        dim3 grid((out_cols + TILE - 1) / TILE, NROWS);
        rsi_v11<<<grid, TPB>>>(in, out, out_cols);
    } else {
        if (w < 1)    w = 1;
        if (w > MAXW) w = MAXW;
        dim3 grid((out_cols + TPB - 1) / TPB, NROWS);
        rsi_generic<<<grid, TPB>>>(in, out, out_cols, w);
    }
}

// round 12
// speedup vs baseline: 1.1311x; 1.1311x over previous
#include <cuda_runtime.h>

// RSI fused single pass, v12 = v8 consolidated. out[c] = g/(g+l) over 13-wide
// window of positive/negative relative deltas (0 when no losses in window).
//
// v8 skeleton (best: 29.44us). Strictly-subtractive edits only:
//  - publish p[0..11] only (p[12..15] never read by neighbors): 3 STS.128
//  - lane31's x16 taken from lane0's halo xe via shuffle (deletes 1 LDG)
//  - TPB=128: warps independent, finer occupancy granularity (36 vs 32 warps)
// Lessons kept: no shuffle exchange (R7), no launch_bounds cap / in-loop LDS
// staging (R9), no alignment-phase store specialization (R10/R11).

#define NROWS  2048
#define NCOLS  8192
#define TPB    128
#define NWARP  (TPB / 32)
#define ITEMS  16
#define WTILE  512               // outputs per warp
#define TILE   (NWARP * WTILE)   // 2048 outputs per block
#define MAXW   64
#define SLOT   20                // smem floats per lane slot (16 data + 4 pad)
#define PREG   (SLOT * 33)       // 32 lanes + halo slot

__global__ __launch_bounds__(TPB) void rsi_v12(
    const float* __restrict__ in,
    float* __restrict__ out,
    int out_cols)
{
    __shared__ __align__(16) float s_p[NWARP * PREG];

    const int tid   = threadIdx.x;
    const int lane  = tid & 31;
    const int wrp   = tid >> 5;
    const int row   = blockIdx.y;
    const int wbase = blockIdx.x * TILE + wrp * WTILE;   // warp's first column
    const float* rin = in + (size_t)row * NCOLS;
    float* pw = s_p + wrp * PREG;
    float* myslot = pw + SLOT * lane;

    const bool edge = (wbase + WTILE) > out_cols;        // last warp of the row

    // ---- load own 16 inputs (wbase+512 <= 8192: always in-row) ----
    const int g0 = wbase + ITEMS * lane;
    const float4 xA = *(const float4*)(rin + g0);
    const float4 xB = *(const float4*)(rin + g0 + 4);
    const float4 xC = *(const float4*)(rin + g0 + 8);
    const float4 xD = *(const float4*)(rin + g0 + 12);

    // halo x: lanes 0..12 load x[wbase+512+lane] (zero past row end)
    float xe = 0.0f;
    if (lane < 13) {
        const int ge = wbase + WTILE + lane;
        xe = (ge < NCOLS) ? rin[ge] : 0.0f;
    }
    const float xen = __shfl_down_sync(0xffffffffu, xe, 1);

    // x[g0+16]: neighbor's first x; lane 31 takes lane 0's halo value
    const float x16n = __shfl_down_sync(0xffffffffu, xA.x, 1);
    const float x16h = __shfl_sync(0xffffffffu, xe, 0);  // x[wbase+512]
    const float x16  = (lane == 31) ? x16h : x16n;

    // ---- own 16 p-values ----
    const float xs[17] = {xA.x, xA.y, xA.z, xA.w, xB.x, xB.y, xB.z, xB.w,
                          xC.x, xC.y, xC.z, xC.w, xD.x, xD.y, xD.z, xD.w, x16};
    float p[ITEMS];
    #pragma unroll
    for (int c = 0; c < ITEMS; ++c) {
        const float prev = xs[c];
        p[c] = (prev != 0.0f) ? __fdividef(xs[c + 1] - prev, prev) : 0.0f;
    }

    // ---- publish p[0..11] (p[12..15] never read by neighbors) ----
    *(float4*)(myslot)     = make_float4(p[0], p[1], p[2],  p[3]);
    *(float4*)(myslot + 4) = make_float4(p[4], p[5], p[6],  p[7]);
    *(float4*)(myslot + 8) = make_float4(p[8], p[9], p[10], p[11]);
    if (lane < 12) {                                     // halo p -> slot 32
        const float pe = (xe != 0.0f) ? __fdividef(xen - xe, xe) : 0.0f;
        pw[SLOT * 32 + lane] = pe;
    }
    __syncwarp();

    // ---- fetch 12 neighbor p-values (lane 31 hits halo slot 32) ----
    const float* nb = pw + SLOT * (lane + 1);
    const float4 n0 = *(const float4*)(nb);
    const float4 n1 = *(const float4*)(nb + 4);
    const float4 n2 = *(const float4*)(nb + 8);
    __syncwarp();                                        // reads done before overwrite

    const float v[ITEMS + 12] = {
        p[0], p[1], p[2],  p[3],  p[4],  p[5],  p[6],  p[7],
        p[8], p[9], p[10], p[11], p[12], p[13], p[14], p[15],
        n0.x, n0.y, n0.z, n0.w, n1.x, n1.y, n1.z, n1.w, n2.x, n2.y, n2.z, n2.w};

    // ---- 16 sliding 13-windows.
    // L: prefix + snapshot (bitwise-exact l==0). S: sliding signed window.
    float S = 0.0f, L = 0.0f;
    float ql[ITEMS], ov4[4];
    #pragma unroll
    for (int j = 0; j < ITEMS + 12; ++j) {
        if (j < ITEMS) ql[j] = L;
        L += fmaxf(-v[j], 0.0f);
        S += v[j];
        if (j >= 13) S -= v[j - 13];
        if (j >= 12) {
            const int k = j - 12;
            const float l = L - ql[k];                   // exact over window
            const float t = S + l;                       // g = S + l
            ov4[k & 3] = (l != 0.0f) ? __fdividef(t, t + l) : 0.0f;
            if ((k & 3) == 3)                            // pad region / consumed p
                *(float4*)(myslot + (k - 3)) =
                    make_float4(ov4[0], ov4[1], ov4[2], ov4[3]);
        }
    }
    __syncwarp();

    // ---- coalesced scalar stores from transposed smem ----
    float* rout = out + (size_t)row * out_cols;
    if (!edge) {
        #pragma unroll
        for (int m = 0; m < ITEMS; ++m) {
            const int o = lane + 32 * m;
            rout[wbase + o] = pw[SLOT * (o >> 4) + (o & 15)];
        }
    } else {
        #pragma unroll
        for (int m = 0; m < ITEMS; ++m) {
            const int o = lane + 32 * m;
            const int col = wbase + o;
            if (col < out_cols)
                rout[col] = pw[SLOT * (o >> 4) + (o & 15)];
        }
    }
}

// ---- Generic fallback for unexpected window sizes ----
__global__ __launch_bounds__(256) void rsi_generic(
    const float* __restrict__ in,
    float* __restrict__ out,
    int out_cols, int w)
{
    __shared__ float s_in[256 + MAXW + 1];
    __shared__ float s_g [256 + MAXW];
    __shared__ float s_l [256 + MAXW];

    const int row  = blockIdx.y;
    const int base = blockIdx.x * 256;
    const float* rin = in + (size_t)row * NCOLS;

    const int need_in = 256 + w + 1;
    for (int i = threadIdx.x; i < need_in; i += 256) {
        const int col = base + i;
        s_in[i] = (col < NCOLS) ? rin[col] : 0.0f;
    }
    __syncthreads();

    const int need_p = 256 + w;
    for (int i = threadIdx.x; i < need_p; i += 256) {
        const float prev = s_in[i];
        const float cur  = s_in[i + 1];
        const float p = (prev != 0.0f) ? (cur - prev) / prev : 0.0f;
        s_g[i] = fmaxf(p, 0.0f);
        s_l[i] = fmaxf(-p, 0.0f);
    }
    __syncthreads();

    const int c = base + threadIdx.x;
    if (c < out_cols) {
        float g = 0.0f, l = 0.0f;
        for (int j = 0; j < w; ++j) {
            g += s_g[threadIdx.x + j];
            l += s_l[threadIdx.x + j];
        }
        out[(size_t)row * out_cols + c] = (l != 0.0f) ? g / (g + l) : 0.0f;
    }
}

extern "C" void kernel_launch(void* const* d_in, const int* in_sizes, int n_in,
                              void* d_out, int out_size)
{
    const float* in  = (const float*)d_in[0];
    float*       out = (float*)d_out;

    const int out_cols = out_size / NROWS;   // NCOLS - (window_size - 1)
    int w = NCOLS - out_cols;

    if (w == 13) {
        dim3 grid((out_cols + TILE - 1) / TILE, NROWS);
        rsi_v12<<<grid, TPB>>>(in, out, out_cols);
    } else {
        if (w < 1)    w = 1;
        if (w > MAXW) w = MAXW;
        dim3 grid((out_cols + 255) / 256, NROWS);
        rsi_generic<<<grid, 256>>>(in, out, out_cols, w);
    }
}